// round 14
// baseline (speedup 1.0000x reference)
#include <cuda_runtime.h>
#include <cuda_bf16.h>
#include <cuda_fp16.h>
#include <mma.h>
#include <math.h>

// ---------------------------------------------------------------------------
// RITS / BRITS-style recurrent imputation. B=512, T=128, D=H=128.
// Launches: prep(+denom), mergedGEMM(wmma), betaGEMM(wmma), seq  (4 total)
// seq R14: Phase E (gate GEMM [4,256]@[256,512]) on tensor cores via
// wmma m8n32k16, fp16 activations staged in SMEM, fp32 accum.
// B/C/F unchanged (fp32 FFMA2 k-split partials).
// ---------------------------------------------------------------------------

#define T_STEPS  128
#define DD       128

typedef unsigned long long ull;

__device__ __align__(16) float  g_Gh[8388608];      // [BT, 128] fp32 (seq reads)
__device__ __align__(16) __half g_Gx16[8388608];    // [BT, 128] fp16 (beta input)
__device__ __align__(16) float  g_Beta[8388608];    // [BT, 128] fp32
__device__ __align__(16) float  g_Gm[33554432];     // [BT, 512] fp32 (no bias)
__device__ __align__(16) float  g_den[128];
__device__ __align__(16) float  g_WhrQ[16384];      // [32 k4][128 j][4 e] fp32
__device__ __align__(16) float  g_WfrQ[16384];      // [32 k4][128 j][4 e] fp32
__device__ __align__(16) __half g_Wgk16[131072];    // [256 k][512 n] fp16 row-major
__device__ __align__(16) __half g_Wk16[65536];      // [128 k][512 n] fp16 (Gm wmma)
__device__ __align__(16) __half g_WthT16[16384];    // [128 k][128 j] fp16
__device__ __align__(16) __half g_WtxT16[16384];    // [128 k][128 j] fp16
__device__ __align__(16) __half g_Wwc16[32768];     // [256 k][128 j] fp16
__device__ __align__(16) __half g_masks16[8388608]; // [BT, 128] fp16 (exact 0/1)
__device__ __align__(16) __half g_deltas16[8388608];// [BT, 128] fp16

__device__ __forceinline__ float sigmoidf_(float x) { return 1.0f / (1.0f + expf(-x)); }

__device__ __forceinline__ void ffma2(ull& d, ull a, ull b) {
    asm("fma.rn.f32x2 %0, %1, %2, %0;" : "+l"(d) : "l"(a), "l"(b));
}
__device__ __forceinline__ float hsum2(ull u) {
    float x, y; asm("mov.b64 {%0, %1}, %2;" : "=f"(x), "=f"(y) : "l"(u));
    return x + y;
}

// ---------------------------------------------------------------------------
// Prep: repacks + fp16 conversions + denom
// ---------------------------------------------------------------------------
__global__ void prep_weights(const float* __restrict__ Wth, const float* __restrict__ Wtx,
                             const float* __restrict__ Whr, const float* __restrict__ Wfr,
                             const float* __restrict__ Wk,  const float* __restrict__ Wr,
                             const float* __restrict__ Wwc,
                             const float* __restrict__ masks, const float* __restrict__ deltas,
                             float* __restrict__ WhrQ, float* __restrict__ WfrQ,
                             __half* __restrict__ Wgk16, __half* __restrict__ Wk16,
                             __half* __restrict__ WthT16, __half* __restrict__ WtxT16,
                             __half* __restrict__ Wwc16,
                             __half* __restrict__ masks16, __half* __restrict__ deltas16,
                             float* __restrict__ den)
{
    int idx = blockIdx.x * blockDim.x + threadIdx.x;
    if (idx < 16384) {
        int k = idx >> 7, j = idx & 127;
        WthT16[idx] = __float2half(Wth[j * 128 + k]);
        WtxT16[idx] = __float2half(Wtx[j * 128 + k]);
        int k4 = idx >> 9, rem = idx & 511, jj = rem >> 2, e = rem & 3;
        int kk = 4 * k4 + e;
        WhrQ[idx] = Whr[kk * 128 + jj];
        WfrQ[idx] = Wfr[jj * 128 + kk];
    }
    if (idx < 32768) {
        Wwc16[idx] = __float2half(Wwc[idx]);     // [256][128] row-major
    }
    if (idx < 131072) {
        // Wgk16[k*512+n], k<128 -> Wk top half, k>=128 -> Wr
        int k = idx >> 9, n = idx & 511;
        float v = (k < 128) ? Wk[k * 512 + n] : Wr[(k - 128) * 512 + n];
        Wgk16[idx] = __float2half(v);
    }
    if (idx < 65536) {
        Wk16[idx] = __float2half(Wk[65536 + idx]);   // mask half, row-major
    }
    for (int i = idx; i < 8388608; i += 131072) {
        masks16[i]  = __float2half(masks[i]);
        deltas16[i] = __float2half(deltas[i]);
    }

    if (blockIdx.x < 128) {
        int t = blockIdx.x;
        float s = 0.0f;
        for (int i = threadIdx.x; i < 512 * 128; i += blockDim.x) {
            int b = i >> 7, d = i & 127;
            s += masks[((size_t)b * T_STEPS + t) * DD + d];
        }
        __shared__ float red[256];
        red[threadIdx.x] = s;
        __syncthreads();
        for (int off = 128; off > 0; off >>= 1) {
            if (threadIdx.x < off) red[threadIdx.x] += red[threadIdx.x + off];
            __syncthreads();
        }
        if (threadIdx.x == 0) den[t] = red[0] + 1e-6f;
    }
}

// ---------------------------------------------------------------------------
// wmma helpers for precompute (unchanged from R13)
// ---------------------------------------------------------------------------
using namespace nvcuda;
typedef wmma::fragment<wmma::accumulator, 16, 16, 16, float> AccFrag;

__device__ __forceinline__ void wmma_accum_k128(
    AccFrag acc[2][2], const __half* __restrict__ A, int lda,
    const __half* __restrict__ B, int bm)
{
    const int w  = threadIdx.x >> 5;
    const int r0 = (w & 1) * 32;
    const int c0 = (w >> 1) * 32;
    for (int k = 0; k < 128; k += 16) {
        wmma::fragment<wmma::matrix_a, 16, 16, 16, __half, wmma::row_major> af[2];
        wmma::fragment<wmma::matrix_b, 16, 16, 16, __half, wmma::row_major> bf[2];
        wmma::load_matrix_sync(af[0], A + (size_t)(bm + r0 +  0) * lda + k, lda);
        wmma::load_matrix_sync(af[1], A + (size_t)(bm + r0 + 16) * lda + k, lda);
        wmma::load_matrix_sync(bf[0], B + (size_t)k * 128 + c0,      128);
        wmma::load_matrix_sync(bf[1], B + (size_t)k * 128 + c0 + 16, 128);
#pragma unroll
        for (int i = 0; i < 2; i++)
#pragma unroll
            for (int jn = 0; jn < 2; jn++)
                wmma::mma_sync(acc[i][jn], af[i], bf[jn], acc[i][jn]);
    }
}

__device__ __forceinline__ void wmma_store_stage(AccFrag acc[2][2], float* stage)
{
    const int w  = threadIdx.x >> 5;
    const int r0 = (w & 1) * 32;
    const int c0 = (w >> 1) * 32;
#pragma unroll
    for (int i = 0; i < 2; i++)
#pragma unroll
        for (int jn = 0; jn < 2; jn++)
            wmma::store_matrix_sync(stage + (size_t)(r0 + i * 16) * 128 + c0 + jn * 16,
                                    acc[i][jn], 128, wmma::mem_row_major);
}

__device__ __forceinline__ void gemm_gm_wmma(
    const __half* __restrict__ A16, const __half* __restrict__ B16,
    float* __restrict__ C, int bm, int bn)
{
    const int w  = threadIdx.x >> 5;
    const int row0 = bm + (w & 1) * 32;
    const int col0 = bn + (w >> 1) * 32;

    AccFrag acc[2][2];
#pragma unroll
    for (int i = 0; i < 2; i++)
#pragma unroll
        for (int jn = 0; jn < 2; jn++)
            wmma::fill_fragment(acc[i][jn], 0.0f);

    for (int k = 0; k < 128; k += 16) {
        wmma::fragment<wmma::matrix_a, 16, 16, 16, __half, wmma::row_major> af[2];
        wmma::fragment<wmma::matrix_b, 16, 16, 16, __half, wmma::row_major> bf[2];
        wmma::load_matrix_sync(af[0], A16 + (size_t)(row0 +  0) * 128 + k, 128);
        wmma::load_matrix_sync(af[1], A16 + (size_t)(row0 + 16) * 128 + k, 128);
        wmma::load_matrix_sync(bf[0], B16 + (size_t)k * 512 + col0,      512);
        wmma::load_matrix_sync(bf[1], B16 + (size_t)k * 512 + col0 + 16, 512);
#pragma unroll
        for (int i = 0; i < 2; i++)
#pragma unroll
            for (int jn = 0; jn < 2; jn++)
                wmma::mma_sync(acc[i][jn], af[i], bf[jn], acc[i][jn]);
    }

#pragma unroll
    for (int i = 0; i < 2; i++)
#pragma unroll
        for (int jn = 0; jn < 2; jn++)
            wmma::store_matrix_sync(C + (size_t)(row0 + i * 16) * 512 + col0 + jn * 16,
                                    acc[i][jn], 512, wmma::mem_row_major);
}

__global__ void __launch_bounds__(256) gemm_merged(
    const __half* __restrict__ deltas16, const __half* __restrict__ masks16,
    const __half* __restrict__ WthT16, const float* __restrict__ bth,
    const __half* __restrict__ WtxT16, const float* __restrict__ btx,
    const __half* __restrict__ Wk16,
    float* __restrict__ Gh, __half* __restrict__ Gx16, float* __restrict__ Gm)
{
    __shared__ __align__(16) float stage[64 * 128];
    const int bm = blockIdx.x * 64;
    const int y = blockIdx.y;
    const int tid = threadIdx.x;

    if (y >= 2) {
        gemm_gm_wmma(masks16, Wk16, Gm, bm, (y - 2) * 128);
        return;
    }

    AccFrag acc[2][2];
#pragma unroll
    for (int i = 0; i < 2; i++)
#pragma unroll
        for (int jn = 0; jn < 2; jn++)
            wmma::fill_fragment(acc[i][jn], 0.0f);

    wmma_accum_k128(acc, deltas16, 128, (y == 0) ? WthT16 : WtxT16, bm);
    wmma_store_stage(acc, stage);
    __syncthreads();

    const float* bias = (y == 0) ? bth : btx;
    for (int i = tid; i < 64 * 128; i += 256) {
        int r = i >> 7, c = i & 127;
        float v = stage[i] + bias[c];
        float g = expf(-fmaxf(v, 0.0f));
        if (y == 0) Gh[(size_t)(bm + r) * 128 + c] = g;
        else        Gx16[(size_t)(bm + r) * 128 + c] = __float2half(g);
    }
}

__global__ void __launch_bounds__(256) gemm_beta(
    const __half* __restrict__ Gx16, const __half* __restrict__ masks16,
    const __half* __restrict__ Wwc16, const float* __restrict__ bwc,
    float* __restrict__ Beta)
{
    __shared__ __align__(16) float stage[64 * 128];
    const int bm = blockIdx.x * 64;
    const int tid = threadIdx.x;

    AccFrag acc[2][2];
#pragma unroll
    for (int i = 0; i < 2; i++)
#pragma unroll
        for (int jn = 0; jn < 2; jn++)
            wmma::fill_fragment(acc[i][jn], 0.0f);

    wmma_accum_k128(acc, Gx16,    128, Wwc16,             bm);
    wmma_accum_k128(acc, masks16, 128, Wwc16 + 128 * 128, bm);
    wmma_store_stage(acc, stage);
    __syncthreads();

    for (int i = tid; i < 64 * 128; i += 256) {
        int r = i >> 7, c = i & 127;
        Beta[(size_t)(bm + r) * 128 + c] = stage[i] + bwc[c];
    }
}

// ---------------------------------------------------------------------------
// Sequential recurrence: 128 CTAs x 4 rows x 512 threads.
// B/C: fp32 FFMA2 k-split partials (unchanged).
// E:   wmma m8n32k16 — a16[8][256] fp16 (cc | h, rows 4-7 zero) @ Wgk16.
// ---------------------------------------------------------------------------
__global__ void __launch_bounds__(512, 1) seq_kernel(
    const float* __restrict__ values, const float* __restrict__ masks,
    const float* __restrict__ WhrQ_g, const float* __restrict__ bhr,
    const float* __restrict__ bfr,    const float* __restrict__ WfrQ_g,
    const float* __restrict__ Gh,     const float* __restrict__ Beta,
    const float* __restrict__ Gm,     const float* __restrict__ den,
    const float* __restrict__ bl,
    const float* __restrict__ Wd,     const float* __restrict__ bd,
    const float* __restrict__ Wo,     const float* __restrict__ bo,
    const __half* __restrict__ Wgk16,
    float* __restrict__ out_pred, float* __restrict__ out_imp,
    float* __restrict__ out_loss)
{
    extern __shared__ float sm[];
    float*  sWhrQ = sm;                 // 16384
    float*  sWfrQ = sm + 16384;         // 16384
    float*  sh    = sm + 32768;         // 512
    float*  sxc   = sm + 33280;         // 512
    float*  scc   = sm + 33792;         // 512
    float*  pp    = sm + 34304;         // 4096 (B/C partials use 2048; E gates use 4096)
    float*  sbhr  = sm + 38400;         // 128
    float*  sbfr  = sm + 38528;         // 128
    __half* a16   = (__half*)(sm + 38656);  // [8][256] fp16 = 1024 floats
    // total 39680 floats = 158,720 B

    const int tid = threadIdx.x;
    const int b0 = blockIdx.x * 4;

    for (int i = tid; i < 16384; i += 512) { sWhrQ[i] = WhrQ_g[i]; sWfrQ[i] = WfrQ_g[i]; }
    if (tid < 128) { sbhr[tid] = bhr[tid]; sbfr[tid] = bfr[tid]; }
    if (tid < 512) sh[tid] = 0.0f;
    // zero all of a16 once (rows 4-7 stay zero forever)
    for (int i = tid; i < 1024; i += 512) ((float*)a16)[i] = 0.0f;

    const int j  = tid & 127;
    const int q  = tid >> 7;
    const size_t rowbase = (size_t)(b0 + q) * T_STEPS;

    float creg = 0.0f;
    float lsum = 0.0f;

    float blv[4];
#pragma unroll
    for (int mm = 0; mm < 4; mm++) blv[mm] = bl[j + 128 * mm];

    float cx = values[rowbase * DD + j];
    float cm = masks[rowbase * DD + j];
    float cb = Beta[rowbase * DD + j];
    float cden = den[0];

    // h(0) = 0: a16 h-columns already zeroed above.

    for (int t = 0; t < T_STEPS; t++) {
        __syncthreads();                                   // S1

        float gmv[4];
#pragma unroll
        for (int mm = 0; mm < 4; mm++)
            gmv[mm] = Gm[(rowbase + t) * 512 + j + 128 * mm];

        int tn = (t + 1 < T_STEPS) ? (t + 1) : (T_STEPS - 1);
        float nx = values[(rowbase + tn) * DD + j];
        float nm = masks[(rowbase + tn) * DD + j];
        float ng = Gh[(rowbase + tn) * DD + j];
        float nb = Beta[(rowbase + tn) * DD + j];
        float nden = den[tn];

        // --- Phase B partials: k in [32q, 32q+32), all 4 rows ---
        {
            ull a0 = 0ULL, a1 = 0ULL, a2 = 0ULL, a3 = 0ULL;
#pragma unroll
            for (int k4 = 0; k4 < 8; k4++) {
                ulonglong2 w = *(const ulonglong2*)&sWhrQ[(q * 8 + k4) * 512 + j * 4];
                int ko = q * 32 + k4 * 4;
                ulonglong2 v0 = *(const ulonglong2*)&sh[0 * 128 + ko];
                ulonglong2 v1 = *(const ulonglong2*)&sh[1 * 128 + ko];
                ulonglong2 v2 = *(const ulonglong2*)&sh[2 * 128 + ko];
                ulonglong2 v3 = *(const ulonglong2*)&sh[3 * 128 + ko];
                ffma2(a0, v0.x, w.x); ffma2(a0, v0.y, w.y);
                ffma2(a1, v1.x, w.x); ffma2(a1, v1.y, w.y);
                ffma2(a2, v2.x, w.x); ffma2(a2, v2.y, w.y);
                ffma2(a3, v3.x, w.x); ffma2(a3, v3.y, w.y);
            }
            pp[q * 512 + 0 * 128 + j] = hsum2(a0);
            pp[q * 512 + 1 * 128 + j] = hsum2(a1);
            pp[q * 512 + 2 * 128 + j] = hsum2(a2);
            pp[q * 512 + 3 * 128 + j] = hsum2(a3);
        }
        __syncthreads();                                   // S2a

        float xh = sbhr[j] + pp[0 * 512 + q * 128 + j] + pp[1 * 512 + q * 128 + j]
                           + pp[2 * 512 + q * 128 + j] + pp[3 * 512 + q * 128 + j];
        float x = cx, m = cm;
        float rd = 1.0f / cden;
        float xc = m * x + (1.0f - m) * xh;
        sxc[q * 128 + j] = xc;
        lsum += fabsf(x - xh) * m * rd;
        __syncthreads();                                   // S2b

        // --- Phase C partials ---
        {
            ull a0 = 0ULL, a1 = 0ULL, a2 = 0ULL, a3 = 0ULL;
#pragma unroll
            for (int k4 = 0; k4 < 8; k4++) {
                ulonglong2 w = *(const ulonglong2*)&sWfrQ[(q * 8 + k4) * 512 + j * 4];
                int ko = q * 32 + k4 * 4;
                ulonglong2 v0 = *(const ulonglong2*)&sxc[0 * 128 + ko];
                ulonglong2 v1 = *(const ulonglong2*)&sxc[1 * 128 + ko];
                ulonglong2 v2 = *(const ulonglong2*)&sxc[2 * 128 + ko];
                ulonglong2 v3 = *(const ulonglong2*)&sxc[3 * 128 + ko];
                ffma2(a0, v0.x, w.x); ffma2(a0, v0.y, w.y);
                ffma2(a1, v1.x, w.x); ffma2(a1, v1.y, w.y);
                ffma2(a2, v2.x, w.x); ffma2(a2, v2.y, w.y);
                ffma2(a3, v3.x, w.x); ffma2(a3, v3.y, w.y);
            }
            pp[q * 512 + 0 * 128 + j] = hsum2(a0);
            pp[q * 512 + 1 * 128 + j] = hsum2(a1);
            pp[q * 512 + 2 * 128 + j] = hsum2(a2);
            pp[q * 512 + 3 * 128 + j] = hsum2(a3);
        }
        __syncthreads();                                   // S3a

        float zh = sbfr[j] + pp[0 * 512 + q * 128 + j] + pp[1 * 512 + q * 128 + j]
                           + pp[2 * 512 + q * 128 + j] + pp[3 * 512 + q * 128 + j];
        lsum += fabsf(x - zh) * m * rd;
        float be = cb;
        float ch = be * zh + (1.0f - be) * xh;
        lsum += fabsf(x - ch) * m * rd;
        float cc = m * x + (1.0f - m) * ch;
        scc[q * 128 + j] = cc;
        a16[q * 256 + j] = __float2half(cc);               // E operand (cc half)
        out_imp[(rowbase + t) * DD + j] = cc;
        __syncthreads();                                   // S3b

        // --- Phase E: gates[8][512] = a16[8][256] @ Wgk16[256][512] (wmma) ---
        {
            const int w = tid >> 5;                        // 0..15 -> n-tile
            const int col0 = w * 32;
            wmma::fragment<wmma::accumulator, 8, 32, 16, float> eaccA, eaccB;
            wmma::fill_fragment(eaccA, 0.0f);
            wmma::fill_fragment(eaccB, 0.0f);
#pragma unroll
            for (int k = 0; k < 256; k += 32) {
                wmma::fragment<wmma::matrix_a, 8, 32, 16, __half, wmma::row_major> afA, afB;
                wmma::fragment<wmma::matrix_b, 8, 32, 16, __half, wmma::row_major> bfA, bfB;
                wmma::load_matrix_sync(afA, a16 + k, 256);
                wmma::load_matrix_sync(bfA, Wgk16 + (size_t)k * 512 + col0, 512);
                wmma::load_matrix_sync(afB, a16 + k + 16, 256);
                wmma::load_matrix_sync(bfB, Wgk16 + (size_t)(k + 16) * 512 + col0, 512);
                wmma::mma_sync(eaccA, afA, bfA, eaccA);
                wmma::mma_sync(eaccB, afB, bfB, eaccB);
            }
#pragma unroll
            for (int e = 0; e < eaccA.num_elements; e++)
                eaccA.x[e] += eaccB.x[e];
            // gates rows 0..7 (rows 4-7 garbage/zero, ignored) -> pp[ r*512 + n ]
            wmma::store_matrix_sync(pp + col0, eaccA, 512, wmma::mem_row_major);
        }
        __syncthreads();                                   // S4

        // --- Phase F: Gm + bl + gates + LSTM update + decay(t+1) ---
        {
            float gi = gmv[0] + blv[0] + pp[q * 512 + j];
            float gf = gmv[1] + blv[1] + pp[q * 512 + 128 + j];
            float gg = gmv[2] + blv[2] + pp[q * 512 + 256 + j];
            float go = gmv[3] + blv[3] + pp[q * 512 + 384 + j];
            float cn = sigmoidf_(gf) * creg + sigmoidf_(gi) * tanhf(gg);
            creg = cn;
            float ho = sigmoidf_(go) * tanhf(cn);
            float dec = (t == T_STEPS - 1) ? 1.0f : ng;
            float hnew = ho * dec;
            sh[q * 128 + j] = hnew;
            a16[q * 256 + 128 + j] = __float2half(hnew);   // E operand (h half)
        }

        cx = nx; cm = nm; cb = nb; cden = nden;
    }

    __syncthreads();

    // --- custom_loss ---
    pp[q * 128 + j] = lsum;
    __syncthreads();
    if (tid < 4) {
        float s = 0.0f;
        for (int k = 0; k < 128; k++) s += pp[tid * 128 + k];
        out_loss[b0 + tid] = s * (1.0f / T_STEPS);
    }
    __syncthreads();

    // --- predictions = relu(h @ Wd + bd) @ Wo + bo ---
    float pa = bd[j];
    for (int k = 0; k < 128; k++)
        pa = fmaf(sh[q * 128 + k], Wd[k * DD + j], pa);
    pp[q * 128 + j] = fmaxf(pa, 0.0f) * Wo[j];
    __syncthreads();
    if (tid < 4) {
        float s = 0.0f;
        for (int k = 0; k < 128; k++) s += pp[tid * 128 + k];
        out_pred[b0 + tid] = s + bo[0];
    }
}

// ---------------------------------------------------------------------------
extern "C" void kernel_launch(void* const* d_in, const int* in_sizes, int n_in,
                              void* d_out, int out_size)
{
    const float* values = (const float*)d_in[0];
    const float* masks  = (const float*)d_in[1];
    const float* deltas = (const float*)d_in[2];
    const float* Wth    = (const float*)d_in[3];
    const float* bth    = (const float*)d_in[4];
    const float* Wtx    = (const float*)d_in[5];
    const float* btx    = (const float*)d_in[6];
    const float* Whr    = (const float*)d_in[7];
    const float* bhr    = (const float*)d_in[8];
    const float* Wfr    = (const float*)d_in[9];
    const float* bfr    = (const float*)d_in[10];
    const float* Wwc    = (const float*)d_in[11];
    const float* bwc    = (const float*)d_in[12];
    const float* Wk     = (const float*)d_in[13];
    const float* Wr     = (const float*)d_in[14];
    const float* bl     = (const float*)d_in[15];
    const float* Wd     = (const float*)d_in[16];
    const float* bd     = (const float*)d_in[17];
    const float* Wo     = (const float*)d_in[18];
    const float* bo     = (const float*)d_in[19];

    float *pGh, *pBeta, *pGm, *pDen, *pWhrQ, *pWfrQ;
    __half *pWgk16, *pWk16, *pMasks16, *pDeltas16, *pGx16, *pWthT16, *pWtxT16, *pWwc16;
    cudaGetSymbolAddress((void**)&pGh,      g_Gh);
    cudaGetSymbolAddress((void**)&pGx16,    g_Gx16);
    cudaGetSymbolAddress((void**)&pBeta,    g_Beta);
    cudaGetSymbolAddress((void**)&pGm,      g_Gm);
    cudaGetSymbolAddress((void**)&pDen,     g_den);
    cudaGetSymbolAddress((void**)&pWhrQ,    g_WhrQ);
    cudaGetSymbolAddress((void**)&pWfrQ,    g_WfrQ);
    cudaGetSymbolAddress((void**)&pWgk16,   g_Wgk16);
    cudaGetSymbolAddress((void**)&pWk16,    g_Wk16);
    cudaGetSymbolAddress((void**)&pWthT16,  g_WthT16);
    cudaGetSymbolAddress((void**)&pWtxT16,  g_WtxT16);
    cudaGetSymbolAddress((void**)&pWwc16,   g_Wwc16);
    cudaGetSymbolAddress((void**)&pMasks16, g_masks16);
    cudaGetSymbolAddress((void**)&pDeltas16,g_deltas16);

    // Launch 0: prep
    prep_weights<<<512, 256>>>(Wth, Wtx, Whr, Wfr, Wk, Wr, Wwc, masks, deltas,
                               pWhrQ, pWfrQ, pWgk16, pWk16,
                               pWthT16, pWtxT16, pWwc16,
                               pMasks16, pDeltas16, pDen);

    // Launch 1: merged GEMM (Gh, Gx16, Gm — all wmma)
    dim3 gm(1024, 6);
    gemm_merged<<<gm, 256>>>(pDeltas16, pMasks16, pWthT16, bth, pWtxT16, btx,
                             pWk16, pGh, pGx16, pGm);

    // Launch 2: Beta (wmma, consumes Gx16)
    gemm_beta<<<1024, 256>>>(pGx16, pMasks16, pWwc16, bwc, pBeta);

    // Launch 3: sequential recurrence
    float* out = (float*)d_out;
    const size_t SMEM = (size_t)39680 * sizeof(float);   // 158,720 B
    cudaFuncSetAttribute(seq_kernel, cudaFuncAttributeMaxDynamicSharedMemorySize, (int)SMEM);
    seq_kernel<<<128, 512, SMEM>>>(values, masks, pWhrQ, bhr, bfr, pWfrQ,
                                   pGh, pBeta, pGm, pDen, bl,
                                   Wd, bd, Wo, bo, pWgk16,
                                   out,                     // predictions [512]
                                   out + 512,               // imputations [512*128*128]
                                   out + 512 + 8388608);    // custom_loss [512]
}

// round 15
// speedup vs baseline: 1.8985x; 1.8985x over previous
#include <cuda_runtime.h>
#include <cuda_bf16.h>
#include <cuda_fp16.h>
#include <mma.h>
#include <math.h>

// ---------------------------------------------------------------------------
// RITS / BRITS-style recurrent imputation. B=512, T=128, D=H=128.
// Launches: prep(+denom), mergedGEMM(wmma), betaGEMM(wmma), seq  (4 total)
// seq R15 = R13 structure with Whr/Wfr stored fp16 in SMEM:
//   - halves B/C weight-LDS wavefronts
//   - SMEM 154.6 -> 89.1 KB => L1D carveout 74 -> 139 KB (better Wg16 hits)
// Phase E = R13 FFMA2 version (R14's in-seq wmma reverted: global fragment
// loads are scattered 2B LDGs -> L1tex explosion).
// ---------------------------------------------------------------------------

#define T_STEPS  128
#define DD       128

typedef unsigned long long ull;

__device__ __align__(16) float  g_Gh[8388608];      // [BT, 128] fp32 (seq reads)
__device__ __align__(16) __half g_Gx16[8388608];    // [BT, 128] fp16 (beta input)
__device__ __align__(16) float  g_Beta[8388608];    // [BT, 128] fp32
__device__ __align__(16) float  g_Gm[33554432];     // [BT, 512] fp32 (no bias)
__device__ __align__(16) float  g_den[128];
__device__ __align__(16) __half g_WhrH[16384];      // [16 k8][128 j][8 e] fp16
__device__ __align__(16) __half g_WfrH[16384];      // [16 k8][128 j][8 e] fp16
__device__ __align__(16) __half g_Wg16[131072];     // [32 k8][512 n][8 e] fp16 (seq E)
__device__ __align__(16) __half g_Wk16[65536];      // [128 k][512 n] fp16 (Gm wmma)
__device__ __align__(16) __half g_WthT16[16384];    // [128 k][128 j] fp16
__device__ __align__(16) __half g_WtxT16[16384];    // [128 k][128 j] fp16
__device__ __align__(16) __half g_Wwc16[32768];     // [256 k][128 j] fp16
__device__ __align__(16) __half g_masks16[8388608]; // [BT, 128] fp16 (exact 0/1)
__device__ __align__(16) __half g_deltas16[8388608];// [BT, 128] fp16

__device__ __forceinline__ float sigmoidf_(float x) { return 1.0f / (1.0f + expf(-x)); }

__device__ __forceinline__ void ffma2(ull& d, ull a, ull b) {
    asm("fma.rn.f32x2 %0, %1, %2, %0;" : "+l"(d) : "l"(a), "l"(b));
}
__device__ __forceinline__ ull packf2(float a, float b) {
    ull u; asm("mov.b64 %0, {%1, %2};" : "=l"(u) : "f"(a), "f"(b)); return u;
}
__device__ __forceinline__ float hsum2(ull u) {
    float x, y; asm("mov.b64 {%0, %1}, %2;" : "=f"(x), "=f"(y) : "l"(u));
    return x + y;
}
// 8 fp16 weights -> 4 packed f32x2 operands
__device__ __forceinline__ void cvt8(uint4 w, ull& u0, ull& u1, ull& u2, ull& u3) {
    const __half2* h = reinterpret_cast<const __half2*>(&w);
    float2 f0 = __half22float2(h[0]);
    float2 f1 = __half22float2(h[1]);
    float2 f2 = __half22float2(h[2]);
    float2 f3 = __half22float2(h[3]);
    u0 = packf2(f0.x, f0.y);
    u1 = packf2(f1.x, f1.y);
    u2 = packf2(f2.x, f2.y);
    u3 = packf2(f3.x, f3.y);
}

// ---------------------------------------------------------------------------
// Prep: repacks + fp16 conversions + denom
// ---------------------------------------------------------------------------
__global__ void prep_weights(const float* __restrict__ Wth, const float* __restrict__ Wtx,
                             const float* __restrict__ Whr, const float* __restrict__ Wfr,
                             const float* __restrict__ Wk,  const float* __restrict__ Wr,
                             const float* __restrict__ Wwc,
                             const float* __restrict__ masks, const float* __restrict__ deltas,
                             __half* __restrict__ WhrH, __half* __restrict__ WfrH,
                             __half* __restrict__ Wg16, __half* __restrict__ Wk16,
                             __half* __restrict__ WthT16, __half* __restrict__ WtxT16,
                             __half* __restrict__ Wwc16,
                             __half* __restrict__ masks16, __half* __restrict__ deltas16,
                             float* __restrict__ den)
{
    int idx = blockIdx.x * blockDim.x + threadIdx.x;
    if (idx < 16384) {
        int k = idx >> 7, j = idx & 127;
        WthT16[idx] = __float2half(Wth[j * 128 + k]);
        WtxT16[idx] = __float2half(Wtx[j * 128 + k]);
        // WhrH[(k8*128 + j)*8 + e] = Whr[(8*k8+e)*128 + j]
        int k8 = idx >> 10, rem = idx & 1023, jj = rem >> 3, e = rem & 7;
        int kk = 8 * k8 + e;
        WhrH[idx] = __float2half(Whr[kk * 128 + jj]);
        WfrH[idx] = __float2half(Wfr[jj * 128 + kk]);
    }
    if (idx < 32768) {
        Wwc16[idx] = __float2half(Wwc[idx]);     // [256][128] row-major
    }
    if (idx < 131072) {
        // Wg16[(k8*512 + n)*8 + e], global k = k8*8 + e; Wg = [Wk_top; Wr]
        int k8 = idx >> 12, rem = idx & 4095, n = rem >> 3, e = rem & 7;
        int k = k8 * 8 + e;
        float v = (k < 128) ? Wk[k * 512 + n] : Wr[(k - 128) * 512 + n];
        Wg16[idx] = __float2half(v);
    }
    if (idx < 65536) {
        Wk16[idx] = __float2half(Wk[65536 + idx]);   // mask half, row-major
    }
    for (int i = idx; i < 8388608; i += 131072) {
        masks16[i]  = __float2half(masks[i]);
        deltas16[i] = __float2half(deltas[i]);
    }

    if (blockIdx.x < 128) {
        int t = blockIdx.x;
        float s = 0.0f;
        for (int i = threadIdx.x; i < 512 * 128; i += blockDim.x) {
            int b = i >> 7, d = i & 127;
            s += masks[((size_t)b * T_STEPS + t) * DD + d];
        }
        __shared__ float red[256];
        red[threadIdx.x] = s;
        __syncthreads();
        for (int off = 128; off > 0; off >>= 1) {
            if (threadIdx.x < off) red[threadIdx.x] += red[threadIdx.x + off];
            __syncthreads();
        }
        if (threadIdx.x == 0) den[t] = red[0] + 1e-6f;
    }
}

// ---------------------------------------------------------------------------
// wmma helpers for precompute (unchanged from R13)
// ---------------------------------------------------------------------------
using namespace nvcuda;
typedef wmma::fragment<wmma::accumulator, 16, 16, 16, float> AccFrag;

__device__ __forceinline__ void wmma_accum_k128(
    AccFrag acc[2][2], const __half* __restrict__ A, int lda,
    const __half* __restrict__ B, int bm)
{
    const int w  = threadIdx.x >> 5;
    const int r0 = (w & 1) * 32;
    const int c0 = (w >> 1) * 32;
    for (int k = 0; k < 128; k += 16) {
        wmma::fragment<wmma::matrix_a, 16, 16, 16, __half, wmma::row_major> af[2];
        wmma::fragment<wmma::matrix_b, 16, 16, 16, __half, wmma::row_major> bf[2];
        wmma::load_matrix_sync(af[0], A + (size_t)(bm + r0 +  0) * lda + k, lda);
        wmma::load_matrix_sync(af[1], A + (size_t)(bm + r0 + 16) * lda + k, lda);
        wmma::load_matrix_sync(bf[0], B + (size_t)k * 128 + c0,      128);
        wmma::load_matrix_sync(bf[1], B + (size_t)k * 128 + c0 + 16, 128);
#pragma unroll
        for (int i = 0; i < 2; i++)
#pragma unroll
            for (int jn = 0; jn < 2; jn++)
                wmma::mma_sync(acc[i][jn], af[i], bf[jn], acc[i][jn]);
    }
}

__device__ __forceinline__ void wmma_store_stage(AccFrag acc[2][2], float* stage)
{
    const int w  = threadIdx.x >> 5;
    const int r0 = (w & 1) * 32;
    const int c0 = (w >> 1) * 32;
#pragma unroll
    for (int i = 0; i < 2; i++)
#pragma unroll
        for (int jn = 0; jn < 2; jn++)
            wmma::store_matrix_sync(stage + (size_t)(r0 + i * 16) * 128 + c0 + jn * 16,
                                    acc[i][jn], 128, wmma::mem_row_major);
}

__device__ __forceinline__ void gemm_gm_wmma(
    const __half* __restrict__ A16, const __half* __restrict__ B16,
    float* __restrict__ C, int bm, int bn)
{
    const int w  = threadIdx.x >> 5;
    const int row0 = bm + (w & 1) * 32;
    const int col0 = bn + (w >> 1) * 32;

    AccFrag acc[2][2];
#pragma unroll
    for (int i = 0; i < 2; i++)
#pragma unroll
        for (int jn = 0; jn < 2; jn++)
            wmma::fill_fragment(acc[i][jn], 0.0f);

    for (int k = 0; k < 128; k += 16) {
        wmma::fragment<wmma::matrix_a, 16, 16, 16, __half, wmma::row_major> af[2];
        wmma::fragment<wmma::matrix_b, 16, 16, 16, __half, wmma::row_major> bf[2];
        wmma::load_matrix_sync(af[0], A16 + (size_t)(row0 +  0) * 128 + k, 128);
        wmma::load_matrix_sync(af[1], A16 + (size_t)(row0 + 16) * 128 + k, 128);
        wmma::load_matrix_sync(bf[0], B16 + (size_t)k * 512 + col0,      512);
        wmma::load_matrix_sync(bf[1], B16 + (size_t)k * 512 + col0 + 16, 512);
#pragma unroll
        for (int i = 0; i < 2; i++)
#pragma unroll
            for (int jn = 0; jn < 2; jn++)
                wmma::mma_sync(acc[i][jn], af[i], bf[jn], acc[i][jn]);
    }

#pragma unroll
    for (int i = 0; i < 2; i++)
#pragma unroll
        for (int jn = 0; jn < 2; jn++)
            wmma::store_matrix_sync(C + (size_t)(row0 + i * 16) * 512 + col0 + jn * 16,
                                    acc[i][jn], 512, wmma::mem_row_major);
}

__global__ void __launch_bounds__(256) gemm_merged(
    const __half* __restrict__ deltas16, const __half* __restrict__ masks16,
    const __half* __restrict__ WthT16, const float* __restrict__ bth,
    const __half* __restrict__ WtxT16, const float* __restrict__ btx,
    const __half* __restrict__ Wk16,
    float* __restrict__ Gh, __half* __restrict__ Gx16, float* __restrict__ Gm)
{
    __shared__ __align__(16) float stage[64 * 128];
    const int bm = blockIdx.x * 64;
    const int y = blockIdx.y;
    const int tid = threadIdx.x;

    if (y >= 2) {
        gemm_gm_wmma(masks16, Wk16, Gm, bm, (y - 2) * 128);
        return;
    }

    AccFrag acc[2][2];
#pragma unroll
    for (int i = 0; i < 2; i++)
#pragma unroll
        for (int jn = 0; jn < 2; jn++)
            wmma::fill_fragment(acc[i][jn], 0.0f);

    wmma_accum_k128(acc, deltas16, 128, (y == 0) ? WthT16 : WtxT16, bm);
    wmma_store_stage(acc, stage);
    __syncthreads();

    const float* bias = (y == 0) ? bth : btx;
    for (int i = tid; i < 64 * 128; i += 256) {
        int r = i >> 7, c = i & 127;
        float v = stage[i] + bias[c];
        float g = expf(-fmaxf(v, 0.0f));
        if (y == 0) Gh[(size_t)(bm + r) * 128 + c] = g;
        else        Gx16[(size_t)(bm + r) * 128 + c] = __float2half(g);
    }
}

__global__ void __launch_bounds__(256) gemm_beta(
    const __half* __restrict__ Gx16, const __half* __restrict__ masks16,
    const __half* __restrict__ Wwc16, const float* __restrict__ bwc,
    float* __restrict__ Beta)
{
    __shared__ __align__(16) float stage[64 * 128];
    const int bm = blockIdx.x * 64;
    const int tid = threadIdx.x;

    AccFrag acc[2][2];
#pragma unroll
    for (int i = 0; i < 2; i++)
#pragma unroll
        for (int jn = 0; jn < 2; jn++)
            wmma::fill_fragment(acc[i][jn], 0.0f);

    wmma_accum_k128(acc, Gx16,    128, Wwc16,             bm);
    wmma_accum_k128(acc, masks16, 128, Wwc16 + 128 * 128, bm);
    wmma_store_stage(acc, stage);
    __syncthreads();

    for (int i = tid; i < 64 * 128; i += 256) {
        int r = i >> 7, c = i & 127;
        Beta[(size_t)(bm + r) * 128 + c] = stage[i] + bwc[c];
    }
}

// ---------------------------------------------------------------------------
// Sequential recurrence: 128 CTAs x 4 rows x 512 threads, k-split partials.
// B/C weights fp16 in SMEM (cvt8 unpack); Phase E = R13 FFMA2 fp16-weight.
// SMEM total 89,088 B -> L1D carveout ~139 KB for the Wg16 stream.
// ---------------------------------------------------------------------------
__global__ void __launch_bounds__(512, 1) seq_kernel(
    const float* __restrict__ values, const float* __restrict__ masks,
    const __half* __restrict__ WhrH_g, const float* __restrict__ bhr,
    const float* __restrict__ bfr,     const __half* __restrict__ WfrH_g,
    const float* __restrict__ Gh,     const float* __restrict__ Beta,
    const float* __restrict__ Gm,     const float* __restrict__ den,
    const float* __restrict__ bl,
    const float* __restrict__ Wd,     const float* __restrict__ bd,
    const float* __restrict__ Wo,     const float* __restrict__ bo,
    const __half* __restrict__ Wg16,
    float* __restrict__ out_pred, float* __restrict__ out_imp,
    float* __restrict__ out_loss)
{
    extern __shared__ float sm[];
    __half* sWhrH = (__half*)sm;            // 16384 halves = 8192 float-slots
    __half* sWfrH = (__half*)(sm + 8192);   // 16384 halves
    float*  sh    = sm + 16384;             // 512
    float*  sxc   = sm + 16896;             // 512
    float*  scc   = sm + 17408;             // 512
    float*  pp    = sm + 17920;             // 4096 partials
    float*  sbhr  = sm + 22016;             // 128
    float*  sbfr  = sm + 22144;             // 128
    // total 22272 floats = 89,088 B

    const int tid = threadIdx.x;
    const int b0 = blockIdx.x * 4;

    for (int i = tid; i < 16384; i += 512) { sWhrH[i] = WhrH_g[i]; sWfrH[i] = WfrH_g[i]; }
    if (tid < 128) { sbhr[tid] = bhr[tid]; sbfr[tid] = bfr[tid]; }
    if (tid < 512) sh[tid] = 0.0f;

    const int j  = tid & 127;
    const int q  = tid >> 7;            // row (reduce phases) == k-group (partials)
    const int ec = tid & 255;           // E column base
    const int eg = tid >> 8;            // E k-half (0: cc/Wk_top, 1: h/Wr)
    const size_t rowbase = (size_t)(b0 + q) * T_STEPS;

    float creg = 0.0f;
    float lsum = 0.0f;

    float blv[4];
#pragma unroll
    for (int mm = 0; mm < 4; mm++) blv[mm] = bl[j + 128 * mm];

    float cx = values[rowbase * DD + j];
    float cm = masks[rowbase * DD + j];
    float cb = Beta[rowbase * DD + j];
    float cden = den[0];

    for (int t = 0; t < T_STEPS; t++) {
        __syncthreads();                                   // S1

        float gmv[4];
#pragma unroll
        for (int mm = 0; mm < 4; mm++)
            gmv[mm] = Gm[(rowbase + t) * 512 + j + 128 * mm];

        int tn = (t + 1 < T_STEPS) ? (t + 1) : (T_STEPS - 1);
        float nx = values[(rowbase + tn) * DD + j];
        float nm = masks[(rowbase + tn) * DD + j];
        float ng = Gh[(rowbase + tn) * DD + j];
        float nb = Beta[(rowbase + tn) * DD + j];
        float nden = den[tn];

        // --- Phase B partials: k in [32q, 32q+32), all 4 rows (fp16 W) ---
        {
            ull a0 = 0ULL, a1 = 0ULL, a2 = 0ULL, a3 = 0ULL;
#pragma unroll
            for (int k8 = 0; k8 < 4; k8++) {
                uint4 wraw = *(const uint4*)&sWhrH[(((q * 4 + k8) * 128) + j) * 8];
                ull w0, w1, w2, w3;
                cvt8(wraw, w0, w1, w2, w3);
                int ko = q * 32 + k8 * 8;
                ulonglong2 v0L = *(const ulonglong2*)&sh[0 * 128 + ko];
                ulonglong2 v0H = *(const ulonglong2*)&sh[0 * 128 + ko + 4];
                ulonglong2 v1L = *(const ulonglong2*)&sh[1 * 128 + ko];
                ulonglong2 v1H = *(const ulonglong2*)&sh[1 * 128 + ko + 4];
                ulonglong2 v2L = *(const ulonglong2*)&sh[2 * 128 + ko];
                ulonglong2 v2H = *(const ulonglong2*)&sh[2 * 128 + ko + 4];
                ulonglong2 v3L = *(const ulonglong2*)&sh[3 * 128 + ko];
                ulonglong2 v3H = *(const ulonglong2*)&sh[3 * 128 + ko + 4];
                ffma2(a0, v0L.x, w0); ffma2(a0, v0L.y, w1); ffma2(a0, v0H.x, w2); ffma2(a0, v0H.y, w3);
                ffma2(a1, v1L.x, w0); ffma2(a1, v1L.y, w1); ffma2(a1, v1H.x, w2); ffma2(a1, v1H.y, w3);
                ffma2(a2, v2L.x, w0); ffma2(a2, v2L.y, w1); ffma2(a2, v2H.x, w2); ffma2(a2, v2H.y, w3);
                ffma2(a3, v3L.x, w0); ffma2(a3, v3L.y, w1); ffma2(a3, v3H.x, w2); ffma2(a3, v3H.y, w3);
            }
            pp[q * 512 + 0 * 128 + j] = hsum2(a0);
            pp[q * 512 + 1 * 128 + j] = hsum2(a1);
            pp[q * 512 + 2 * 128 + j] = hsum2(a2);
            pp[q * 512 + 3 * 128 + j] = hsum2(a3);
        }
        __syncthreads();                                   // S2a

        float xh = sbhr[j] + pp[0 * 512 + q * 128 + j] + pp[1 * 512 + q * 128 + j]
                           + pp[2 * 512 + q * 128 + j] + pp[3 * 512 + q * 128 + j];
        float x = cx, m = cm;
        float rd = 1.0f / cden;
        float xc = m * x + (1.0f - m) * xh;
        sxc[q * 128 + j] = xc;
        lsum += fabsf(x - xh) * m * rd;
        __syncthreads();                                   // S2b

        // --- Phase C partials (fp16 W) ---
        {
            ull a0 = 0ULL, a1 = 0ULL, a2 = 0ULL, a3 = 0ULL;
#pragma unroll
            for (int k8 = 0; k8 < 4; k8++) {
                uint4 wraw = *(const uint4*)&sWfrH[(((q * 4 + k8) * 128) + j) * 8];
                ull w0, w1, w2, w3;
                cvt8(wraw, w0, w1, w2, w3);
                int ko = q * 32 + k8 * 8;
                ulonglong2 v0L = *(const ulonglong2*)&sxc[0 * 128 + ko];
                ulonglong2 v0H = *(const ulonglong2*)&sxc[0 * 128 + ko + 4];
                ulonglong2 v1L = *(const ulonglong2*)&sxc[1 * 128 + ko];
                ulonglong2 v1H = *(const ulonglong2*)&sxc[1 * 128 + ko + 4];
                ulonglong2 v2L = *(const ulonglong2*)&sxc[2 * 128 + ko];
                ulonglong2 v2H = *(const ulonglong2*)&sxc[2 * 128 + ko + 4];
                ulonglong2 v3L = *(const ulonglong2*)&sxc[3 * 128 + ko];
                ulonglong2 v3H = *(const ulonglong2*)&sxc[3 * 128 + ko + 4];
                ffma2(a0, v0L.x, w0); ffma2(a0, v0L.y, w1); ffma2(a0, v0H.x, w2); ffma2(a0, v0H.y, w3);
                ffma2(a1, v1L.x, w0); ffma2(a1, v1L.y, w1); ffma2(a1, v1H.x, w2); ffma2(a1, v1H.y, w3);
                ffma2(a2, v2L.x, w0); ffma2(a2, v2L.y, w1); ffma2(a2, v2H.x, w2); ffma2(a2, v2H.y, w3);
                ffma2(a3, v3L.x, w0); ffma2(a3, v3L.y, w1); ffma2(a3, v3H.x, w2); ffma2(a3, v3H.y, w3);
            }
            pp[q * 512 + 0 * 128 + j] = hsum2(a0);
            pp[q * 512 + 1 * 128 + j] = hsum2(a1);
            pp[q * 512 + 2 * 128 + j] = hsum2(a2);
            pp[q * 512 + 3 * 128 + j] = hsum2(a3);
        }
        __syncthreads();                                   // S3a

        float zh = sbfr[j] + pp[0 * 512 + q * 128 + j] + pp[1 * 512 + q * 128 + j]
                           + pp[2 * 512 + q * 128 + j] + pp[3 * 512 + q * 128 + j];
        lsum += fabsf(x - zh) * m * rd;
        float be = cb;
        float ch = be * zh + (1.0f - be) * xh;
        lsum += fabsf(x - ch) * m * rd;
        float cc = m * x + (1.0f - m) * ch;
        scc[q * 128 + j] = cc;
        out_imp[(rowbase + t) * DD + j] = cc;
        __syncthreads();                                   // S3b

        // --- Phase E partials: cols {ec, ec+256}, k-half eg, 4 rows, fp16 W ---
        {
            const float* src = (eg == 0) ? scc : sh;
            const __half* w16 = Wg16 + (size_t)eg * 16 * 512 * 8;
            ull e0 = 0ULL, e1 = 0ULL, e2 = 0ULL, e3 = 0ULL;
            ull e4 = 0ULL, e5 = 0ULL, e6 = 0ULL, e7 = 0ULL;
#pragma unroll 2
            for (int i = 0; i < 16; i++) {
                uint4 wa_raw = *(const uint4*)&w16[((size_t)i * 512 + ec) * 8];
                uint4 wb_raw = *(const uint4*)&w16[((size_t)i * 512 + ec + 256) * 8];
                ull wa0, wa1, wa2, wa3, wb0, wb1, wb2, wb3;
                cvt8(wa_raw, wa0, wa1, wa2, wa3);
                cvt8(wb_raw, wb0, wb1, wb2, wb3);
                int ko = i * 8;
                ulonglong2 v0L = *(const ulonglong2*)&src[0 * 128 + ko];
                ulonglong2 v0H = *(const ulonglong2*)&src[0 * 128 + ko + 4];
                ulonglong2 v1L = *(const ulonglong2*)&src[1 * 128 + ko];
                ulonglong2 v1H = *(const ulonglong2*)&src[1 * 128 + ko + 4];
                ulonglong2 v2L = *(const ulonglong2*)&src[2 * 128 + ko];
                ulonglong2 v2H = *(const ulonglong2*)&src[2 * 128 + ko + 4];
                ulonglong2 v3L = *(const ulonglong2*)&src[3 * 128 + ko];
                ulonglong2 v3H = *(const ulonglong2*)&src[3 * 128 + ko + 4];
                ffma2(e0, v0L.x, wa0); ffma2(e0, v0L.y, wa1); ffma2(e0, v0H.x, wa2); ffma2(e0, v0H.y, wa3);
                ffma2(e1, v1L.x, wa0); ffma2(e1, v1L.y, wa1); ffma2(e1, v1H.x, wa2); ffma2(e1, v1H.y, wa3);
                ffma2(e2, v2L.x, wa0); ffma2(e2, v2L.y, wa1); ffma2(e2, v2H.x, wa2); ffma2(e2, v2H.y, wa3);
                ffma2(e3, v3L.x, wa0); ffma2(e3, v3L.y, wa1); ffma2(e3, v3H.x, wa2); ffma2(e3, v3H.y, wa3);
                ffma2(e4, v0L.x, wb0); ffma2(e4, v0L.y, wb1); ffma2(e4, v0H.x, wb2); ffma2(e4, v0H.y, wb3);
                ffma2(e5, v1L.x, wb0); ffma2(e5, v1L.y, wb1); ffma2(e5, v1H.x, wb2); ffma2(e5, v1H.y, wb3);
                ffma2(e6, v2L.x, wb0); ffma2(e6, v2L.y, wb1); ffma2(e6, v2H.x, wb2); ffma2(e6, v2H.y, wb3);
                ffma2(e7, v3L.x, wb0); ffma2(e7, v3L.y, wb1); ffma2(e7, v3H.x, wb2); ffma2(e7, v3H.y, wb3);
            }
            pp[eg * 2048 + 0 * 512 + ec] = hsum2(e0);
            pp[eg * 2048 + 1 * 512 + ec] = hsum2(e1);
            pp[eg * 2048 + 2 * 512 + ec] = hsum2(e2);
            pp[eg * 2048 + 3 * 512 + ec] = hsum2(e3);
            pp[eg * 2048 + 0 * 512 + ec + 256] = hsum2(e4);
            pp[eg * 2048 + 1 * 512 + ec + 256] = hsum2(e5);
            pp[eg * 2048 + 2 * 512 + ec + 256] = hsum2(e6);
            pp[eg * 2048 + 3 * 512 + ec + 256] = hsum2(e7);
        }
        __syncthreads();                                   // S4

        // --- Phase F: Gm + bl + reduce own gates + LSTM update + decay(t+1) ---
        {
            float gi = gmv[0] + blv[0] + pp[q * 512 + j]        + pp[2048 + q * 512 + j];
            float gf = gmv[1] + blv[1] + pp[q * 512 + 128 + j]  + pp[2048 + q * 512 + 128 + j];
            float gg = gmv[2] + blv[2] + pp[q * 512 + 256 + j]  + pp[2048 + q * 512 + 256 + j];
            float go = gmv[3] + blv[3] + pp[q * 512 + 384 + j]  + pp[2048 + q * 512 + 384 + j];
            float cn = sigmoidf_(gf) * creg + sigmoidf_(gi) * tanhf(gg);
            creg = cn;
            float ho = sigmoidf_(go) * tanhf(cn);
            float dec = (t == T_STEPS - 1) ? 1.0f : ng;
            sh[q * 128 + j] = ho * dec;
        }

        cx = nx; cm = nm; cb = nb; cden = nden;
    }

    __syncthreads();

    // --- custom_loss ---
    pp[q * 128 + j] = lsum;
    __syncthreads();
    if (tid < 4) {
        float s = 0.0f;
        for (int k = 0; k < 128; k++) s += pp[tid * 128 + k];
        out_loss[b0 + tid] = s * (1.0f / T_STEPS);
    }
    __syncthreads();

    // --- predictions = relu(h @ Wd + bd) @ Wo + bo ---
    float pa = bd[j];
    for (int k = 0; k < 128; k++)
        pa = fmaf(sh[q * 128 + k], Wd[k * DD + j], pa);
    pp[q * 128 + j] = fmaxf(pa, 0.0f) * Wo[j];
    __syncthreads();
    if (tid < 4) {
        float s = 0.0f;
        for (int k = 0; k < 128; k++) s += pp[tid * 128 + k];
        out_pred[b0 + tid] = s + bo[0];
    }
}

// ---------------------------------------------------------------------------
extern "C" void kernel_launch(void* const* d_in, const int* in_sizes, int n_in,
                              void* d_out, int out_size)
{
    const float* values = (const float*)d_in[0];
    const float* masks  = (const float*)d_in[1];
    const float* deltas = (const float*)d_in[2];
    const float* Wth    = (const float*)d_in[3];
    const float* bth    = (const float*)d_in[4];
    const float* Wtx    = (const float*)d_in[5];
    const float* btx    = (const float*)d_in[6];
    const float* Whr    = (const float*)d_in[7];
    const float* bhr    = (const float*)d_in[8];
    const float* Wfr    = (const float*)d_in[9];
    const float* bfr    = (const float*)d_in[10];
    const float* Wwc    = (const float*)d_in[11];
    const float* bwc    = (const float*)d_in[12];
    const float* Wk     = (const float*)d_in[13];
    const float* Wr     = (const float*)d_in[14];
    const float* bl     = (const float*)d_in[15];
    const float* Wd     = (const float*)d_in[16];
    const float* bd     = (const float*)d_in[17];
    const float* Wo     = (const float*)d_in[18];
    const float* bo     = (const float*)d_in[19];

    float *pGh, *pBeta, *pGm, *pDen;
    __half *pWhrH, *pWfrH, *pWg16, *pWk16, *pMasks16, *pDeltas16, *pGx16,
           *pWthT16, *pWtxT16, *pWwc16;
    cudaGetSymbolAddress((void**)&pGh,      g_Gh);
    cudaGetSymbolAddress((void**)&pGx16,    g_Gx16);
    cudaGetSymbolAddress((void**)&pBeta,    g_Beta);
    cudaGetSymbolAddress((void**)&pGm,      g_Gm);
    cudaGetSymbolAddress((void**)&pDen,     g_den);
    cudaGetSymbolAddress((void**)&pWhrH,    g_WhrH);
    cudaGetSymbolAddress((void**)&pWfrH,    g_WfrH);
    cudaGetSymbolAddress((void**)&pWg16,    g_Wg16);
    cudaGetSymbolAddress((void**)&pWk16,    g_Wk16);
    cudaGetSymbolAddress((void**)&pWthT16,  g_WthT16);
    cudaGetSymbolAddress((void**)&pWtxT16,  g_WtxT16);
    cudaGetSymbolAddress((void**)&pWwc16,   g_Wwc16);
    cudaGetSymbolAddress((void**)&pMasks16, g_masks16);
    cudaGetSymbolAddress((void**)&pDeltas16,g_deltas16);

    // Launch 0: prep
    prep_weights<<<512, 256>>>(Wth, Wtx, Whr, Wfr, Wk, Wr, Wwc, masks, deltas,
                               pWhrH, pWfrH, pWg16, pWk16,
                               pWthT16, pWtxT16, pWwc16,
                               pMasks16, pDeltas16, pDen);

    // Launch 1: merged GEMM (Gh, Gx16, Gm — all wmma)
    dim3 gm(1024, 6);
    gemm_merged<<<gm, 256>>>(pDeltas16, pMasks16, pWthT16, bth, pWtxT16, btx,
                             pWk16, pGh, pGx16, pGm);

    // Launch 2: Beta (wmma, consumes Gx16)
    gemm_beta<<<1024, 256>>>(pGx16, pMasks16, pWwc16, bwc, pBeta);

    // Launch 3: sequential recurrence
    float* out = (float*)d_out;
    const size_t SMEM = (size_t)22272 * sizeof(float);   // 89,088 B
    cudaFuncSetAttribute(seq_kernel, cudaFuncAttributeMaxDynamicSharedMemorySize, (int)SMEM);
    seq_kernel<<<128, 512, SMEM>>>(values, masks, pWhrH, bhr, bfr, pWfrH,
                                   pGh, pBeta, pGm, pDen, bl,
                                   Wd, bd, Wo, bo, pWg16,
                                   out,                     // predictions [512]
                                   out + 512,               // imputations [512*128*128]
                                   out + 512 + 8388608);    // custom_loss [512]
}